// round 6
// baseline (speedup 1.0000x reference)
#include <cuda_runtime.h>

#define BB 4
#define NPTS 2048
#define HH 128
#define WW 128
#define SPLITS 32
#define KCH (NPTS / SPLITS)   // 64 atoms per block
#define CHUNK 32              // atoms resident in shared at once
#define IMG (BB * HH * WW)    // 65536
#define IMG4 (IMG / 4)        // 16384
#define CLEAN_OFF (IMG + 36)  // clean region start in out (float4-aligned)

#define RED4(ptr, v) \
    asm volatile("red.global.add.v4.f32 [%0], {%1,%2,%3,%4};" \
                 :: "l"(ptr), "f"((v).x), "f"((v).y), "f"((v).z), "f"((v).w) \
                 : "memory")

// ---------------------------------------------------------------------------
// Zero kernel: clear the clean accumulation region, write rot passthrough.
// ---------------------------------------------------------------------------
__global__ void zero_kernel(const float* __restrict__ rot,
                            float* __restrict__ out) {
    int t = blockIdx.x * blockDim.x + threadIdx.x;
    if (t < IMG4)
        *(float4*)&out[CLEAN_OFF + t * 4] = make_float4(0.f, 0.f, 0.f, 0.f);
    if (t < 36) out[IMG + t] = rot[t];
}

// ---------------------------------------------------------------------------
// Fused kernel. Warp w owns output rows [16w, 16w+16). Phase A projects the
// chunk's 32 atoms and ballots per-window atom bitmaps; Phase C iterates only
// atoms whose y-support intersects the warp's window. Epilogue: RED.ADD.v4
// directly into the clean region of out (no partials, no combine).
// ---------------------------------------------------------------------------
__global__ void __launch_bounds__(256) fused_kernel(const float* __restrict__ x,
                                                    const float* __restrict__ rot,
                                                    float* __restrict__ out) {
    int s = blockIdx.x;
    int b = blockIdx.y;

    __shared__ float sfy[CHUNK][128];     // 16KB
    __shared__ float sfx[CHUNK][128];     // 16KB
    __shared__ float spx[CHUNK];
    __shared__ float spy[CHUNK];
    __shared__ unsigned swm[8];           // per-window atom bitmap

    int tid  = threadIdx.x;
    int w    = tid >> 5;        // warp id = row-window id (0..7)
    int lane = tid & 31;
    int rg   = lane >> 4;       // row sub-group (0/1)
    int cx   = lane & 15;       // column group

    const float* R = rot + b * 9;
    float R0 = R[0], R1 = R[1], R2 = R[2];
    float R3 = R[3], R4 = R[4], R5 = R[5];

    float acc[8][8];
#pragma unroll
    for (int i = 0; i < 8; i++)
#pragma unroll
        for (int j = 0; j < 8; j++) acc[i][j] = 0.0f;

    int atom_base = b * NPTS + s * KCH;

    for (int c = 0; c < KCH / CHUNK; c++) {
        // --- Phase A: warp 0 projects 32 atoms, builds window bitmaps ---
        if (tid < 32) {
            const float* xp = x + (atom_base + c * CHUNK + tid) * 3;
            float x0 = xp[0], x1 = xp[1], x2 = xp[2];
            const float scale = 51.2f;
            float px = fmaf(R0, x0, fmaf(R1, x1, R2 * x2)) * scale + 64.0f;
            float py = fmaf(R3, x0, fmaf(R4, x1, R5 * x2)) * scale + 64.0f;
            spx[tid] = px;
            spy[tid] = py;
            int w0 = (int)floorf((py - 12.0f) * 0.0625f);
            int w1 = (int)floorf((py + 12.0f) * 0.0625f);
            if (w0 < 0) w0 = 0;
            if (w1 > 7) w1 = 7;
#pragma unroll
            for (int ww = 0; ww < 8; ww++) {
                unsigned bm = __ballot_sync(0xffffffffu, ww >= w0 && ww <= w1);
                if (tid == ww) swm[ww] = bm;
            }
        }
        __syncthreads();

        // --- Phase B: factor tables (cutoff d^2>=144 -> exp ~ 1e-14) ---
        const float cexp = -0.22222222f;  // -1/(2*1.5^2)
#pragma unroll 4
        for (int i = 0; i < 16; i++) {
            int e = tid + i * 256;
            int a = e >> 7;
            int p = e & 127;
            float fp = (float)p;
            float dx = fp - spx[a];
            float dy = fp - spy[a];
            float qx = dx * dx;
            float qy = dy * dy;
            sfx[a][p] = (qx < 144.0f) ? __expf(qx * cexp) : 0.0f;
            sfy[a][p] = (qy < 144.0f) ? __expf(qy * cexp) : 0.0f;
        }
        __syncthreads();

        // --- Phase C: sparse rank update (only atoms hitting this window) ---
        unsigned m = swm[w];
        while (m) {
            int kk = __ffs(m) - 1;
            m &= m - 1;
            float yv[8], xv[8];
            *(float4*)&yv[0] = *(float4*)&sfy[kk][16 * w + 8 * rg];
            *(float4*)&yv[4] = *(float4*)&sfy[kk][16 * w + 8 * rg + 4];
            *(float4*)&xv[0] = *(float4*)&sfx[kk][cx * 4];
            *(float4*)&xv[4] = *(float4*)&sfx[kk][64 + cx * 4];
#pragma unroll
            for (int i = 0; i < 8; i++)
#pragma unroll
                for (int j = 0; j < 8; j++)
                    acc[i][j] = fmaf(yv[i], xv[j], acc[i][j]);
        }
        __syncthreads();
    }

    // --- Epilogue: reduce into clean region via L2 atomics ---
    float* dst = out + CLEAN_OFF + b * (HH * WW);
#pragma unroll
    for (int i = 0; i < 8; i++) {
        int h = 16 * w + 8 * rg + i;
#pragma unroll
        for (int jj = 0; jj < 2; jj++) {
            int wc = (jj == 0) ? (cx * 4) : (64 + cx * 4);
            float4 v = make_float4(acc[i][jj * 4 + 0], acc[i][jj * 4 + 1],
                                   acc[i][jj * 4 + 2], acc[i][jj * 4 + 3]);
            RED4(dst + h * WW + wc, v);
        }
    }
}

// ---------------------------------------------------------------------------
// Finish: noisy = clean + 0.1 * noise.
// ---------------------------------------------------------------------------
__global__ void finish_kernel(const float* __restrict__ noise,
                              float* __restrict__ out) {
    int t = blockIdx.x * blockDim.x + threadIdx.x;
    if (t >= IMG4) return;
    float4 s  = *(const float4*)&out[CLEAN_OFF + t * 4];
    float4 nz = ((const float4*)noise)[t];
    float4 noisy = make_float4(fmaf(nz.x, 0.1f, s.x), fmaf(nz.y, 0.1f, s.y),
                               fmaf(nz.z, 0.1f, s.z), fmaf(nz.w, 0.1f, s.w));
    ((float4*)out)[t] = noisy;
}

// ---------------------------------------------------------------------------
extern "C" void kernel_launch(void* const* d_in, const int* in_sizes, int n_in,
                              void* d_out, int out_size) {
    const float* x     = (const float*)d_in[0];  // (4,2048,3)
    const float* rot   = (const float*)d_in[1];  // (4,3,3)
    const float* noise = (const float*)d_in[2];  // (4,128,128)
    float* out = (float*)d_out;

    zero_kernel<<<(IMG4 + 255) / 256, 256>>>(rot, out);

    dim3 grid(SPLITS, BB);
    fused_kernel<<<grid, 256>>>(x, rot, out);

    finish_kernel<<<(IMG4 + 255) / 256, 256>>>(noise, out);
}